// round 1
// baseline (speedup 1.0000x reference)
#include <cuda_runtime.h>
#include <cstddef>

// ---------------------------------------------------------------------------
// EuclideanCodebook (VQ) for GB300.
//   x:            (8,4096,128)  f32  -> T=32768 tokens, D=128
//   embed:        (1,8192,128)  f32  -> K=8192 codes
//   cluster_size: (1,8192)      f32
//   embed_avg:    (1,8192,128)  f32
// Outputs (concatenated fp32, reference return order):
//   quantized (T*D) | indices (T) | dist (T*K) | new_embed (K*D)
//   | new_cluster_size (K) | new_embed_avg (K*D)
// ---------------------------------------------------------------------------

#define T_TOK   32768
#define D_DIM   128
#define K_CODE  8192
#define TM      128
#define TN      128
#define NCHUNK  (K_CODE / TN)     // 64
#define SSTRIDE 132               // smem row stride in floats (D-major layout)

// output offsets (elements)
#define OFF_Q    ((size_t)0)
#define OFF_I    ((size_t)4194304)
#define OFF_DIST ((size_t)4227072)
#define OFF_NE   ((size_t)272662528)
#define OFF_NCS  ((size_t)273711104)
#define OFF_NEA  ((size_t)273719296)

// scratch (device globals; no dynamic allocation allowed)
__device__ float g_cs[K_CODE];
__device__ float g_es[K_CODE * D_DIM];
__device__ int   g_idx[T_TOK];
__device__ float g_x2[T_TOK];
__device__ float g_e2[K_CODE];
__device__ float g_total;

// ---- packed f32x2 helpers --------------------------------------------------
__device__ __forceinline__ unsigned long long pk2(float lo, float hi) {
    unsigned long long r;
    asm("mov.b64 %0, {%1, %2};" : "=l"(r)
        : "r"(__float_as_int(lo)), "r"(__float_as_int(hi)));
    return r;
}
__device__ __forceinline__ void upk2(unsigned long long v, float& lo, float& hi) {
    int a, b;
    asm("mov.b64 {%0, %1}, %2;" : "=r"(a), "=r"(b) : "l"(v));
    lo = __int_as_float(a); hi = __int_as_float(b);
}
#define FMA2(c, a, b) \
    asm("fma.rn.f32x2 %0, %1, %2, %0;" : "+l"(c) : "l"(a), "l"(b))

// ---------------------------------------------------------------------------
// zero scratch accumulators
__global__ void k_zero() {
    int i = blockIdx.x * blockDim.x + threadIdx.x;
    if (i < K_CODE * D_DIM) g_es[i] = 0.0f;
    if (i < K_CODE)         g_cs[i] = 0.0f;
    if (i == 0)             g_total = 0.0f;
}

// row norms: |x_t|^2 and |e_k|^2 (one warp per row)
__global__ void k_norms(const float* __restrict__ x, const float* __restrict__ embed) {
    int row  = blockIdx.x * 8 + (threadIdx.x >> 5);
    int lane = threadIdx.x & 31;
    const float* src;
    float* dst;
    if (row < T_TOK) { src = x + (size_t)row * D_DIM;              dst = &g_x2[row]; }
    else             { src = embed + (size_t)(row - T_TOK) * D_DIM; dst = &g_e2[row - T_TOK]; }
    float v0 = src[lane], v1 = src[lane + 32], v2 = src[lane + 64], v3 = src[lane + 96];
    float s = v0 * v0 + v1 * v1 + v2 * v2 + v3 * v3;
    #pragma unroll
    for (int o = 16; o > 0; o >>= 1) s += __shfl_down_sync(0xffffffffu, s, o);
    if (lane == 0) *dst = s;
}

// ---------------------------------------------------------------------------
// main: dist tile (128 tokens x 8192 codes per CTA) + fused argmin.
// dist = (x2 + e2) - 2*dot, matching the reference formula/order.
__global__ void __launch_bounds__(256, 1)
k_dist(const float* __restrict__ x, const float* __restrict__ embed,
       float* __restrict__ out) {
    extern __shared__ float smem[];
    float* xs   = smem;                    // [128][SSTRIDE]  xs[d][r]
    float* es   = xs + D_DIM * SSTRIDE;    // [128][SSTRIDE]  es[d][c]
    float* e2s  = es + D_DIM * SSTRIDE;    // [128]
    float* redv = e2s + TN;                // [128][16]
    int*   redi = (int*)(redv + TM * 16);  // [128][16]

    const int tid  = threadIdx.x;
    const int w    = tid >> 5;
    const int lane = tid & 31;
    const int row0 = blockIdx.x * TM;

    // stage x tile transposed: xs[d][r]
    for (int rr = 0; rr < 16; rr++) {
        int r = w * 16 + rr;
        const float* src = x + (size_t)(row0 + r) * D_DIM;
        #pragma unroll
        for (int q = 0; q < 4; q++) {
            int d = q * 32 + lane;
            xs[d * SSTRIDE + r] = src[d];
        }
    }

    const int ty = tid >> 4, tx = tid & 15;
    const int r0 = ty * 8, c0 = tx * 8;

    float rx2[8];
    #pragma unroll
    for (int i = 0; i < 8; i++) rx2[i] = g_x2[row0 + r0 + i];

    float bmin[8];
    int   barg[8];
    #pragma unroll
    for (int i = 0; i < 8; i++) { bmin[i] = 3.4e38f; barg[i] = 0; }

    float* out_dist = out + OFF_DIST;

    for (int ch = 0; ch < NCHUNK; ch++) {
        const int cbase = ch * TN;
        __syncthreads();
        // stage embed chunk transposed: es[d][c]
        for (int rr = 0; rr < 16; rr++) {
            int c = w * 16 + rr;
            const float* src = embed + (size_t)(cbase + c) * D_DIM;
            #pragma unroll
            for (int q = 0; q < 4; q++) {
                int d = q * 32 + lane;
                es[d * SSTRIDE + c] = src[d];
            }
        }
        if (tid < TN) e2s[tid] = g_e2[cbase + tid];
        __syncthreads();

        // 8x8 register tile via packed f32x2 FMAs
        unsigned long long acc[8][4];
        #pragma unroll
        for (int i = 0; i < 8; i++)
            #pragma unroll
            for (int j = 0; j < 4; j++) acc[i][j] = 0ull;

        #pragma unroll 2
        for (int d = 0; d < D_DIM; d++) {
            float4 a0 = *(const float4*)&xs[d * SSTRIDE + r0];
            float4 a1 = *(const float4*)&xs[d * SSTRIDE + r0 + 4];
            float4 b0 = *(const float4*)&es[d * SSTRIDE + c0];
            float4 b1 = *(const float4*)&es[d * SSTRIDE + c0 + 4];
            unsigned long long B[4] = { pk2(b0.x, b0.y), pk2(b0.z, b0.w),
                                        pk2(b1.x, b1.y), pk2(b1.z, b1.w) };
            float A[8] = { a0.x, a0.y, a0.z, a0.w, a1.x, a1.y, a1.z, a1.w };
            #pragma unroll
            for (int i = 0; i < 8; i++) {
                unsigned long long a2 = pk2(A[i], A[i]);
                #pragma unroll
                for (int j = 0; j < 4; j++) FMA2(acc[i][j], a2, B[j]);
            }
        }

        // epilogue: dist, store, running argmin (scan order = ascending col)
        #pragma unroll
        for (int i = 0; i < 8; i++) {
            float dv[8];
            #pragma unroll
            for (int j = 0; j < 4; j++) upk2(acc[i][j], dv[2 * j], dv[2 * j + 1]);
            #pragma unroll
            for (int j = 0; j < 8; j++) {
                float s = rx2[i] + e2s[c0 + j];
                float d = s - 2.0f * dv[j];
                dv[j] = d;
                if (d < bmin[i]) { bmin[i] = d; barg[i] = cbase + c0 + j; }
            }
            float4* dst = (float4*)&out_dist[(size_t)(row0 + r0 + i) * K_CODE + cbase + c0];
            dst[0] = make_float4(dv[0], dv[1], dv[2], dv[3]);
            dst[1] = make_float4(dv[4], dv[5], dv[6], dv[7]);
        }
    }

    // cross-thread argmin reduction (lowest index wins on ties)
    __syncthreads();
    #pragma unroll
    for (int i = 0; i < 8; i++) {
        redv[(r0 + i) * 16 + tx] = bmin[i];
        redi[(r0 + i) * 16 + tx] = barg[i];
    }
    __syncthreads();
    if (tid < TM) {
        float bv = redv[tid * 16];
        int   bi = redi[tid * 16];
        #pragma unroll
        for (int t = 1; t < 16; t++) {
            float v = redv[tid * 16 + t];
            int   ii = redi[tid * 16 + t];
            if (v < bv || (v == bv && ii < bi)) { bv = v; bi = ii; }
        }
        g_idx[row0 + tid] = bi;
        out[OFF_I + row0 + tid] = (float)bi;
    }
}

// ---------------------------------------------------------------------------
// scatter: segment sums + codebook gather + quantized output
__global__ void k_scatter(const float* __restrict__ x, const float* __restrict__ embed,
                          float* __restrict__ out) {
    int t = blockIdx.x;
    int d = threadIdx.x;
    int idx = g_idx[t];
    float xv = x[(size_t)t * D_DIM + d];
    atomicAdd(&g_es[(size_t)idx * D_DIM + d], xv);
    out[OFF_Q + (size_t)t * D_DIM + d] = embed[(size_t)idx * D_DIM + d];
    if (d == 0) atomicAdd(&g_cs[idx], 1.0f);
}

// new_cluster_size + global sum
__global__ void k_ncs(const float* __restrict__ cs_in, float* __restrict__ out) {
    int k = blockIdx.x * blockDim.x + threadIdx.x;
    float ncs = 0.0f;
    if (k < K_CODE) {
        ncs = 0.1f * cs_in[k] + 0.9f * g_cs[k];
        out[OFF_NCS + k] = ncs;
    }
    #pragma unroll
    for (int o = 16; o > 0; o >>= 1) ncs += __shfl_down_sync(0xffffffffu, ncs, o);
    if ((threadIdx.x & 31) == 0) atomicAdd(&g_total, ncs);
}

// new_embed_avg + laplace-smoothed new_embed
__global__ void k_final(const float* __restrict__ ea_in, float* __restrict__ out) {
    size_t i = (size_t)blockIdx.x * blockDim.x + threadIdx.x;
    if (i >= (size_t)K_CODE * D_DIM) return;
    float nea = 0.1f * ea_in[i] + 0.9f * g_es[i];
    out[OFF_NEA + i] = nea;
    int k = (int)(i >> 7);
    float ncs = out[OFF_NCS + k];
    float normalized = (ncs + 1e-5f) / (g_total + 8192.0f * 1e-5f);
    out[OFF_NE + i] = nea / normalized;
}

// ---------------------------------------------------------------------------
extern "C" void kernel_launch(void* const* d_in, const int* in_sizes, int n_in,
                              void* d_out, int out_size) {
    // resolve inputs by element count (robust to input ordering conventions)
    const float* x = nullptr;
    const float* embed = nullptr;
    const float* cs_in = nullptr;
    const float* ea_in = nullptr;
    for (int i = 0; i < n_in; i++) {
        if (in_sizes[i] == T_TOK * D_DIM) x = (const float*)d_in[i];
        else if (in_sizes[i] == K_CODE)   cs_in = (const float*)d_in[i];
        else if (in_sizes[i] == K_CODE * D_DIM) {
            if (!embed) embed = (const float*)d_in[i];
            else        ea_in = (const float*)d_in[i];
        }
    }
    float* out = (float*)d_out;

    const int smem_bytes = (2 * D_DIM * SSTRIDE + TN + TM * 16 * 2) * 4;
    cudaFuncSetAttribute(k_dist, cudaFuncAttributeMaxDynamicSharedMemorySize, smem_bytes);

    k_zero<<<(K_CODE * D_DIM + 255) / 256, 256>>>();
    k_norms<<<(T_TOK + K_CODE) / 8, 256>>>(x, embed);
    k_dist<<<T_TOK / TM, 256, smem_bytes>>>(x, embed, out);
    k_scatter<<<T_TOK, D_DIM>>>(x, embed, out);
    k_ncs<<<(K_CODE + 255) / 256, 256>>>(cs_in, out);
    k_final<<<(K_CODE * D_DIM + 255) / 256, 256>>>(ea_in, out);
}